// round 3
// baseline (speedup 1.0000x reference)
#include <cuda_runtime.h>
#include <cstdint>

#define NMAX 100000
#define EMAX 1600000
#define F1 512
#define F3 128
#define H 128
#define C 64
#define KTOT (F1 + F3)   // 640
#define SW 0.2f
#define FW 0.8f
#define BN_EPS 1e-5f

// ---------------- device scratch (static, no allocations) ----------------
__device__ int   g_is64;
__device__ int   g_src[EMAX];
__device__ int   g_dst[EMAX];
__device__ int   g_deg[NMAX + 1];
__device__ int   g_off[NMAX + 1];
__device__ int   g_cur[NMAX];
__device__ int   g_bsum[128];
__device__ int   g_adj[EMAX];
__device__ float g_Wc[KTOT * H];      // fused [640,128] weight
__device__ float g_bz[H];
__device__ float g_scale[H];
__device__ float g_shift[H];
__device__ float g_z[(size_t)NMAX * H];     // 51.2 MB
__device__ float g_agg[(size_t)NMAX * H];   // 51.2 MB (post BN+ReLU)
__device__ float g_z2[(size_t)NMAX * C];    // 25.6 MB

// ---------------- edge dtype sniff + decode ----------------
__global__ void k_sniff(const long long* __restrict__ ei) {
    if (threadIdx.x == 0 && blockIdx.x == 0) {
        int ok = 1;
        for (int i = 0; i < 128; i++) {
            long long v = ei[i];
            if (v < 0 || v >= 2147483647LL) { ok = 0; break; }
        }
        g_is64 = ok;
    }
}

__global__ void k_decode(const void* __restrict__ eiv, int E, int n) {
    int e = blockIdx.x * blockDim.x + threadIdx.x;
    if (e >= E) return;
    int s, d;
    if (g_is64) {
        const long long* p = (const long long*)eiv;
        s = (int)__ldg(&p[e]);
        d = (int)__ldg(&p[(size_t)E + e]);
    } else {
        const int* p = (const int*)eiv;
        s = __ldg(&p[e]);
        d = __ldg(&p[(size_t)E + e]);
    }
    s = min(max(s, 0), n - 1);
    d = min(max(d, 0), n - 1);
    g_src[e] = s;
    g_dst[e] = d;
}

// ---------------- CSR build ----------------
__global__ void k_zero(int n) {
    int i = blockIdx.x * blockDim.x + threadIdx.x;
    if (i < n) { g_deg[i] = 0; g_cur[i] = 0; }
}

__global__ void k_hist(int E) {
    int e = blockIdx.x * blockDim.x + threadIdx.x;
    if (e < E) atomicAdd(&g_deg[g_dst[e]], 1);
}

__global__ void k_scan1(int n) {
    __shared__ int sh[1024];
    int t = threadIdx.x;
    int g = blockIdx.x * 1024 + t;
    int v = (g < n) ? g_deg[g] : 0;
    sh[t] = v;
    __syncthreads();
    for (int d = 1; d < 1024; d <<= 1) {
        int x = (t >= d) ? sh[t - d] : 0;
        __syncthreads();
        sh[t] += x;
        __syncthreads();
    }
    if (g < n) g_off[g] = sh[t] - v;       // exclusive within block
    if (t == 1023) g_bsum[blockIdx.x] = sh[1023];
}

__global__ void k_scan2(int nb) {
    __shared__ int sh[128];
    int t = threadIdx.x;
    int v = (t < nb) ? g_bsum[t] : 0;
    sh[t] = v;
    __syncthreads();
    for (int d = 1; d < 128; d <<= 1) {
        int x = (t >= d) ? sh[t - d] : 0;
        __syncthreads();
        sh[t] += x;
        __syncthreads();
    }
    if (t < nb) g_bsum[t] = sh[t] - v;     // exclusive
}

__global__ void k_scan3(int n, int E) {
    int g = blockIdx.x * 1024 + threadIdx.x;
    if (g < n)       g_off[g] += g_bsum[blockIdx.x];
    else if (g == n) g_off[n]  = E;
}

__global__ void k_fill(int E) {
    int e = blockIdx.x * blockDim.x + threadIdx.x;
    if (e >= E) return;
    int dst = g_dst[e];
    int p = atomicAdd(&g_cur[dst], 1);
    g_adj[g_off[dst] + p] = g_src[e];
}

// ---------------- weight / BN precompute ----------------
__global__ void k_precompute(const float* __restrict__ W1, const float* __restrict__ b1,
                             const float* __restrict__ W2, const float* __restrict__ b2,
                             const float* __restrict__ Wg1, const float* __restrict__ bg1,
                             const float* __restrict__ gamma, const float* __restrict__ beta,
                             const float* __restrict__ rmean, const float* __restrict__ rvar) {
    int b = blockIdx.x, j = threadIdx.x;   // j in [0,128)
    if (b < F1) {
        float acc = 0.f;
        #pragma unroll 8
        for (int i = 0; i < H; i++) acc = fmaf(W1[b * H + i], Wg1[i * H + j], acc);
        g_Wc[b * H + j] = FW * acc;
    } else if (b < KTOT) {
        int r = b - F1;
        float acc = 0.f;
        #pragma unroll 8
        for (int i = 0; i < H; i++) acc = fmaf(W2[r * H + i], Wg1[i * H + j], acc);
        g_Wc[b * H + j] = SW * acc;
    } else if (b == KTOT) {
        float acc = 0.f;
        for (int i = 0; i < H; i++) acc = fmaf(FW * b1[i] + SW * b2[i], Wg1[i * H + j], acc);
        g_bz[j] = acc;
    } else {
        float sc = gamma[j] * rsqrtf(rvar[j] + BN_EPS);
        g_scale[j] = sc;
        g_shift[j] = (bg1[j] - rmean[j]) * sc + beta[j];
    }
}

// ---------------- GEMM1: z = [x1|x2] @ Wc + bz   ([N,640]x[640,128]) ----------------
__global__ __launch_bounds__(256) void k_gemm1(const float* __restrict__ x1,
                                               const float* __restrict__ x2, int n) {
    __shared__ float As[16][128];
    __shared__ float Bs[16][128];
    int tid = threadIdx.x;
    int m0 = blockIdx.x * 128;
    int tx = tid & 15, ty = tid >> 4;
    int tn = tx * 8, tm = ty * 8;
    float acc[8][8] = {};

    for (int k0 = 0; k0 < KTOT; k0 += 16) {
        const float* xa;
        int stride, kbase;
        if (k0 < F1) { xa = x1; stride = F1; kbase = k0; }
        else         { xa = x2; stride = F3; kbase = k0 - F1; }
        #pragma unroll
        for (int i = 0; i < 2; i++) {
            int f = tid + i * 256;            // 0..511
            int row = f >> 2;                 // 0..127
            int kq = (f & 3) * 4;             // 0,4,8,12
            int grow = m0 + row;
            float4 v = make_float4(0.f, 0.f, 0.f, 0.f);
            if (grow < n) v = *(const float4*)(xa + (size_t)grow * stride + kbase + kq);
            As[kq + 0][row] = v.x; As[kq + 1][row] = v.y;
            As[kq + 2][row] = v.z; As[kq + 3][row] = v.w;
        }
        #pragma unroll
        for (int i = 0; i < 2; i++) {
            int f = tid + i * 256;
            int row = f >> 5;                 // 0..15
            int cq = (f & 31) * 4;
            *(float4*)&Bs[row][cq] = *(const float4*)(g_Wc + (size_t)(k0 + row) * H + cq);
        }
        __syncthreads();
        #pragma unroll
        for (int k = 0; k < 16; k++) {
            float4 a0 = *(float4*)&As[k][tm];
            float4 a1 = *(float4*)&As[k][tm + 4];
            float4 b0 = *(float4*)&Bs[k][tn];
            float4 b1v = *(float4*)&Bs[k][tn + 4];
            float a[8] = {a0.x, a0.y, a0.z, a0.w, a1.x, a1.y, a1.z, a1.w};
            float b[8] = {b0.x, b0.y, b0.z, b0.w, b1v.x, b1v.y, b1v.z, b1v.w};
            #pragma unroll
            for (int i = 0; i < 8; i++)
                #pragma unroll
                for (int j = 0; j < 8; j++)
                    acc[i][j] = fmaf(a[i], b[j], acc[i][j]);
        }
        __syncthreads();
    }
    #pragma unroll
    for (int i = 0; i < 8; i++) {
        int grow = m0 + tm + i;
        if (grow < n) {
            #pragma unroll
            for (int j = 0; j < 8; j += 4) {
                float4 v;
                v.x = acc[i][j + 0] + g_bz[tn + j + 0];
                v.y = acc[i][j + 1] + g_bz[tn + j + 1];
                v.z = acc[i][j + 2] + g_bz[tn + j + 2];
                v.w = acc[i][j + 3] + g_bz[tn + j + 3];
                *(float4*)(g_z + (size_t)grow * H + tn + j) = v;
            }
        }
    }
}

// ---------------- gather-reduce layer 1 (+ BN + ReLU) ----------------
__global__ __launch_bounds__(256) void k_agg128(int n) {
    int w = (blockIdx.x * blockDim.x + threadIdx.x) >> 5;
    int lane = threadIdx.x & 31;
    if (w >= n) return;
    float4 sc = *(const float4*)(g_scale + lane * 4);
    float4 sh = *(const float4*)(g_shift + lane * 4);
    int s = g_off[w], e = g_off[w + 1];
    float4 acc = make_float4(0.f, 0.f, 0.f, 0.f);
    for (int i = s; i < e; i++) {
        int src = g_adj[i];
        float4 v = *(const float4*)(g_z + (size_t)src * H + lane * 4);
        acc.x += v.x; acc.y += v.y; acc.z += v.z; acc.w += v.w;
    }
    float4 r;
    r.x = fmaxf(fmaf(acc.x, sc.x, sh.x), 0.f);
    r.y = fmaxf(fmaf(acc.y, sc.y, sh.y), 0.f);
    r.z = fmaxf(fmaf(acc.z, sc.z, sh.z), 0.f);
    r.w = fmaxf(fmaf(acc.w, sc.w, sh.w), 0.f);
    *(float4*)(g_agg + (size_t)w * H + lane * 4) = r;
}

// ---------------- GEMM2: z2 = agg @ Wg2   ([N,128]x[128,64]) ----------------
__global__ __launch_bounds__(256) void k_gemm2(const float* __restrict__ Wg2, int n) {
    __shared__ float As[16][128];
    __shared__ float Bs[16][64];
    int tid = threadIdx.x;
    int m0 = blockIdx.x * 128;
    int tx = tid & 15, ty = tid >> 4;
    int tn = tx * 4, tm = ty * 8;
    float acc[8][4] = {};

    for (int k0 = 0; k0 < H; k0 += 16) {
        #pragma unroll
        for (int i = 0; i < 2; i++) {
            int f = tid + i * 256;
            int row = f >> 2;
            int kq = (f & 3) * 4;
            int grow = m0 + row;
            float4 v = make_float4(0.f, 0.f, 0.f, 0.f);
            if (grow < n) v = *(const float4*)(g_agg + (size_t)grow * H + k0 + kq);
            As[kq + 0][row] = v.x; As[kq + 1][row] = v.y;
            As[kq + 2][row] = v.z; As[kq + 3][row] = v.w;
        }
        {
            int row = tid >> 4;           // 0..15
            int cq = (tid & 15) * 4;      // 0..60
            *(float4*)&Bs[row][cq] = *(const float4*)(Wg2 + (size_t)(k0 + row) * C + cq);
        }
        __syncthreads();
        #pragma unroll
        for (int k = 0; k < 16; k++) {
            float4 a0 = *(float4*)&As[k][tm];
            float4 a1 = *(float4*)&As[k][tm + 4];
            float4 bv = *(float4*)&Bs[k][tn];
            float a[8] = {a0.x, a0.y, a0.z, a0.w, a1.x, a1.y, a1.z, a1.w};
            float b[4] = {bv.x, bv.y, bv.z, bv.w};
            #pragma unroll
            for (int i = 0; i < 8; i++)
                #pragma unroll
                for (int j = 0; j < 4; j++)
                    acc[i][j] = fmaf(a[i], b[j], acc[i][j]);
        }
        __syncthreads();
    }
    #pragma unroll
    for (int i = 0; i < 8; i++) {
        int grow = m0 + tm + i;
        if (grow < n) {
            float4 v = make_float4(acc[i][0], acc[i][1], acc[i][2], acc[i][3]);
            *(float4*)(g_z2 + (size_t)grow * C + tn) = v;
        }
    }
}

// ---------------- gather-reduce layer 2 (+ bg2) -> out ----------------
__global__ __launch_bounds__(256) void k_agg64(const float* __restrict__ bg2,
                                               float* __restrict__ out, int n) {
    int w = (blockIdx.x * blockDim.x + threadIdx.x) >> 5;
    int lane = threadIdx.x & 31;
    if (w >= n) return;
    int s = g_off[w], e = g_off[w + 1];
    float2 acc = *(const float2*)(bg2 + lane * 2);
    for (int i = s; i < e; i++) {
        int src = g_adj[i];
        float2 v = *(const float2*)(g_z2 + (size_t)src * C + lane * 2);
        acc.x += v.x; acc.y += v.y;
    }
    *(float2*)(out + (size_t)w * C + lane * 2) = acc;
}

// ---------------- launch ----------------
extern "C" void kernel_launch(void* const* d_in, const int* in_sizes, int n_in,
                              void* d_out, int out_size) {
    const float* x1   = (const float*)d_in[0];
    const float* x2   = (const float*)d_in[1];
    const void*  ei   = (const void*)d_in[2];
    const float* W1   = (const float*)d_in[3];
    const float* b1   = (const float*)d_in[4];
    const float* W2   = (const float*)d_in[5];
    const float* b2   = (const float*)d_in[6];
    const float* Wg1  = (const float*)d_in[7];
    const float* bg1  = (const float*)d_in[8];
    const float* Wg2  = (const float*)d_in[9];
    const float* bg2  = (const float*)d_in[10];
    const float* gamma = (const float*)d_in[11];
    const float* beta  = (const float*)d_in[12];
    const float* rmean = (const float*)d_in[13];
    const float* rvar  = (const float*)d_in[14];
    float* out = (float*)d_out;

    int N = in_sizes[0] / F1;
    int E = in_sizes[2] / 2;

    int scan_blocks = (N + 1023) / 1024;           // covers n
    int scan_blocks3 = (N + 1024) / 1024;          // covers n+1

    // edge decode (dtype-robust) + CSR build
    k_sniff<<<1, 32>>>((const long long*)ei);
    k_decode<<<(E + 255) / 256, 256>>>(ei, E, N);
    k_zero<<<(N + 255) / 256, 256>>>(N);
    k_hist<<<(E + 255) / 256, 256>>>(E);
    k_scan1<<<scan_blocks, 1024>>>(N);
    k_scan2<<<1, 128>>>(scan_blocks);
    k_scan3<<<scan_blocks3, 1024>>>(N, E);
    k_fill<<<(E + 255) / 256, 256>>>(E);

    // weight + BN precompute
    k_precompute<<<KTOT + 2, H>>>(W1, b1, W2, b2, Wg1, bg1, gamma, beta, rmean, rvar);

    int gemm_blocks = (N + 127) / 128;
    int agg_blocks = (N + 7) / 8;                  // 8 warps per 256-thread block

    k_gemm1<<<gemm_blocks, 256>>>(x1, x2, N);
    k_agg128<<<agg_blocks, 256>>>(N);
    k_gemm2<<<gemm_blocks, 256>>>(Wg2, N);
    k_agg64<<<agg_blocks, 256>>>(bg2, out, N);
}